// round 12
// baseline (speedup 1.0000x reference)
#include <cuda_runtime.h>
#include <cuda_fp16.h>
#include <mma.h>
#include <math.h>

using namespace nvcuda;

#define DIM 256
#define TILE_ROWS 256
#define THREADS 512
#define RPB 256   // rows per pool block
#define GPB 16    // graphs per stats block

// smem layout (bytes), 256-row tile:
//  regionA : union( sW1h half[256][136] , sH1h half[256][136] ) = 69632   @ 0
//  sW2h    : half [128][72] = 18432                                        @ 69632
//  regionC : union( sXh half[256][264]=135168 , sH1f float[256][132]=135168,
//                   sH2f float[256][68]=69632 )                            @ 88064
//  sb      : float[257]                                                    @ 223232
#define OFF_A   0
#define OFF_W2  69632
#define OFF_C   88064
#define OFF_B   223232
#define SMEM_BYTES (OFF_B + 1040)

// device scratch (no allocation allowed)
__device__ float g_logits[620000];
__device__ __half g_w1h[2][256 * 128];
__device__ __half g_w2h[2][128 * 64];

// ---------------- weight fp32 -> fp16 pre-convert (once) ----------------
__global__ void convert_w_kernel(const float* __restrict__ W1,
                                 const float* __restrict__ W2,
                                 __half* __restrict__ o1, __half* __restrict__ o2)
{
    int i = blockIdx.x * 256 + threadIdx.x;
    if (i < 256 * 128) o1[i] = __float2half(W1[i]);
    if (i < 128 * 64)  o2[i] = __float2half(W2[i]);
}

// ---------------- MLP logits: 256-row tile, 16 warps ----------------
__global__ void __launch_bounds__(THREADS)
mlp_logits_kernel(const float* __restrict__ X,
                  const __half* __restrict__ W1h, const __half* __restrict__ W2h,
                  const float* __restrict__ b1, const float* __restrict__ b2,
                  const float* __restrict__ W3, const float* __restrict__ b3,
                  float* __restrict__ logits, int nrows)
{
    extern __shared__ char smem[];
    half*  sW1h = (half*)(smem + OFF_A);
    half*  sH1h = (half*)(smem + OFF_A);     // aliases W1 (dead after GEMM1)
    half*  sW2h = (half*)(smem + OFF_W2);
    half*  sXh  = (half*)(smem + OFF_C);
    float* sH1f = (float*)(smem + OFF_C);
    float* sH2f = (float*)(smem + OFF_C);
    float* sb   = (float*)(smem + OFF_B);

    const int tid = threadIdx.x;
    const int w   = tid >> 5;
    const int rowBase = blockIdx.x * TILE_ROWS;

    // ---- stage weights (vectorized copy of pre-converted fp16) ----
    {
        const uint4* W1v = (const uint4*)W1h;   // 4096 uint4
#pragma unroll
        for (int k = 0; k < 8; k++) {
            int idx8 = tid + k * 512;
            int r = idx8 >> 4, c8 = idx8 & 15;
            *(uint4*)(sW1h + r * 136 + c8 * 8) = W1v[idx8];
        }
        const uint4* W2v = (const uint4*)W2h;   // 1024 uint4
#pragma unroll
        for (int k = 0; k < 2; k++) {
            int idx8 = tid + k * 512;
            int r = idx8 >> 3, c8 = idx8 & 7;
            *(uint4*)(sW2h + r * 72 + c8 * 8) = W2v[idx8];
        }
    }
    if (tid < 128) sb[tid] = b1[tid];
    if (tid < 64) {
        sb[128 + tid] = b2[tid];
        sb[192 + tid] = W3[tid];
    }
    if (tid == 0) sb[256] = b3[0];

    // ---- load X tile (fp32 -> fp16), vectorized, zero-pad tail rows ----
    {
        const float4* X4 = (const float4*)X;
#pragma unroll
        for (int k = 0; k < 32; k++) {
            int idx4 = tid + k * 512;            // over 256*64 float4s
            int r = idx4 >> 6, c4 = idx4 & 63;
            int gr = rowBase + r;
            float4 v = make_float4(0.f, 0.f, 0.f, 0.f);
            if (gr < nrows) v = X4[(size_t)gr * 64 + c4];
            half2 h0 = __floats2half2_rn(v.x, v.y);
            half2 h1 = __floats2half2_rn(v.z, v.w);
            uint2 pk;
            pk.x = *(unsigned int*)&h0;
            pk.y = *(unsigned int*)&h1;
            *(uint2*)(sXh + r * 264 + c4 * 4) = pk;
        }
    }
    __syncthreads();

    // ---- GEMM1: H1[256x128] = X[256x256] @ W1[256x128] ----
    // 16 warps: 8 M-groups x 2 N-groups; each warp computes 32 rows x 64 cols
    {
        const int mBase = (w >> 1) * 32;
        const int nBase = (w & 1) * 64;
        wmma::fragment<wmma::accumulator, 16, 16, 16, float> acc[2][4];
#pragma unroll
        for (int m = 0; m < 2; m++)
#pragma unroll
            for (int n = 0; n < 4; n++) wmma::fill_fragment(acc[m][n], 0.0f);
#pragma unroll
        for (int kt = 0; kt < 16; kt++) {
            wmma::fragment<wmma::matrix_a, 16, 16, 16, half, wmma::row_major> a[2];
#pragma unroll
            for (int m = 0; m < 2; m++)
                wmma::load_matrix_sync(a[m], sXh + (mBase + m * 16) * 264 + kt * 16, 264);
#pragma unroll
            for (int n = 0; n < 4; n++) {
                wmma::fragment<wmma::matrix_b, 16, 16, 16, half, wmma::row_major> b;
                wmma::load_matrix_sync(b, sW1h + (kt * 16) * 136 + nBase + n * 16, 136);
#pragma unroll
                for (int m = 0; m < 2; m++)
                    wmma::mma_sync(acc[m][n], a[m], b, acc[m][n]);
            }
        }
        __syncthreads();  // everyone done reading sXh (regionC) and sW1h (regionA)
#pragma unroll
        for (int m = 0; m < 2; m++)
#pragma unroll
            for (int n = 0; n < 4; n++)
                wmma::store_matrix_sync(sH1f + (mBase + m * 16) * 132 + nBase + n * 16,
                                        acc[m][n], 132, wmma::mem_row_major);
    }
    __syncthreads();

    // ---- bias + relu + convert to fp16 (H1h overwrites dead W1 region) ----
    for (int k = 0; k < 32; k++) {
        int i = tid + k * 512;                 // over 256*64 float2 pairs
        int r = i >> 6, c2 = i & 63;
        float2 v = *(const float2*)(sH1f + r * 132 + c2 * 2);
        float b0 = sb[c2 * 2], b1v = sb[c2 * 2 + 1];
        half2 h = __floats2half2_rn(fmaxf(v.x + b0, 0.0f), fmaxf(v.y + b1v, 0.0f));
        *(half2*)(sH1h + r * 136 + c2 * 2) = h;
    }
    __syncthreads();

    // ---- GEMM2: H2[256x64] = H1[256x128] @ W2[128x64]; warp = 16 rows ----
    {
        const int mB2 = w * 16;
        wmma::fragment<wmma::accumulator, 16, 16, 16, float> acc2[4];
#pragma unroll
        for (int n = 0; n < 4; n++) wmma::fill_fragment(acc2[n], 0.0f);
#pragma unroll
        for (int kt = 0; kt < 8; kt++) {
            wmma::fragment<wmma::matrix_a, 16, 16, 16, half, wmma::row_major> a;
            wmma::load_matrix_sync(a, sH1h + mB2 * 136 + kt * 16, 136);
#pragma unroll
            for (int n = 0; n < 4; n++) {
                wmma::fragment<wmma::matrix_b, 16, 16, 16, half, wmma::row_major> b;
                wmma::load_matrix_sync(b, sW2h + (kt * 16) * 72 + n * 16, 72);
                wmma::mma_sync(acc2[n], a, b, acc2[n]);
            }
        }
        // regionC holds dead H1f (last read before previous sync); own rows only
#pragma unroll
        for (int n = 0; n < 4; n++)
            wmma::store_matrix_sync(sH2f + mB2 * 68 + n * 16, acc2[n], 68,
                                    wmma::mem_row_major);
    }
    __syncthreads();

    // ---- layer 3: logit = b3 + sum_c relu(H2 + b2) * W3 ----
    if (tid < 256) {
        int r = tid;
        float acc = sb[256];
#pragma unroll
        for (int c = 0; c < 64; c++) {
            float v = fmaxf(sH2f[r * 68 + c] + sb[128 + c], 0.0f);
            acc = fmaf(v, sb[192 + c], acc);
        }
        int gr = rowBase + r;
        if (gr < nrows) logits[gr] = acc;
    }
}

// ---------------- helpers ----------------
__device__ __forceinline__ int lower_bound_idx(const int* __restrict__ index,
                                               int n, int target)
{
    int lo = 0, hi = n;
    while (lo < hi) {
        int mid = (lo + hi) >> 1;
        if (index[mid] < target) lo = mid + 1; else hi = mid;
    }
    return lo;
}

__device__ __forceinline__ unsigned encf(float f)
{
    unsigned b = __float_as_uint(f);
    return b ^ ((b >> 31) ? 0xFFFFFFFFu : 0x80000000u);
}
__device__ __forceinline__ float decf(unsigned k)
{
    unsigned b = (k >> 31) ? (k ^ 0x80000000u) : (k ^ 0xFFFFFFFFu);
    return __uint_as_float(b);
}

// ---------------- fused segment softmax (max + sum + normalize, in-place) ----------------
__global__ void __launch_bounds__(512)
softmax_kernel(float* __restrict__ logits, const int* __restrict__ index, int n)
{
    __shared__ unsigned smax[GPB];
    __shared__ float ssum[GPB];
    __shared__ int sbound[2];
    const int tid = threadIdx.x;
    const int gbase = blockIdx.x * GPB;

    if (tid < GPB) { smax[tid] = 0u; ssum[tid] = 0.0f; }
    if (tid < 2) sbound[tid] = lower_bound_idx(index, n, gbase + tid * GPB);
    __syncthreads();
    const int s0 = sbound[0], e0 = sbound[1];

    // sweep 1: per-graph max
    for (int i = s0 + tid; i < e0; i += 512) {
        int g = index[i] - gbase;
        atomicMax(&smax[g], encf(logits[i]));
    }
    __syncthreads();
    // sweep 2: exp + sum (stash exp in logits)
    for (int i = s0 + tid; i < e0; i += 512) {
        int g = index[i] - gbase;
        float e = __expf(logits[i] - decf(smax[g]));
        logits[i] = e;
        atomicAdd(&ssum[g], e);
    }
    __syncthreads();
    // sweep 3: normalize
    for (int i = s0 + tid; i < e0; i += 512) {
        int g = index[i] - gbase;
        logits[i] = __fdividef(logits[i], ssum[g]);
    }
}

// ---------------- row-tiled weighted segment sum (float4) ----------------
__global__ void __launch_bounds__(256)
pool_kernel(const float* __restrict__ X, const float* __restrict__ wrow,
            const int* __restrict__ index, float* __restrict__ out, int n)
{
    __shared__ float sw[RPB];
    __shared__ int sstart[2052];
    __shared__ float4 red[4][64];
    const int base = blockIdx.x * RPB;
    const int cnt = min(RPB, n - base);
    const int tid = threadIdx.x;
    const int quad = tid >> 6;       // 0..3 : row phase
    const int dq   = tid & 63;       // dim group (4 floats)

    for (int i = tid; i < cnt; i += 256) sw[i] = wrow[base + i];

    const int g0 = index[base];
    const int g1 = index[base + cnt - 1];
    const int nruns = g1 - g0 + 1;

    for (int t = tid; t < nruns; t += 256) {
        int gs = lower_bound_idx(index, n, g0 + t) - base;
        sstart[t] = max(gs, 0);
    }
    if (tid == 0) sstart[nruns] = cnt;
    __syncthreads();

    const float4* X4 = (const float4*)X;
    for (int run = 0; run < nruns; run++) {
        int rs = sstart[run], re = sstart[run + 1];
        float4 a0 = make_float4(0.f, 0.f, 0.f, 0.f);
        float4 a1 = make_float4(0.f, 0.f, 0.f, 0.f);
        int i = rs + quad;
        for (; i + 4 < re; i += 8) {
            float w0 = sw[i], w1 = sw[i + 4];
            float4 x0 = X4[(size_t)(base + i) * 64 + dq];
            float4 x1 = X4[(size_t)(base + i + 4) * 64 + dq];
            a0.x = fmaf(w0, x0.x, a0.x); a0.y = fmaf(w0, x0.y, a0.y);
            a0.z = fmaf(w0, x0.z, a0.z); a0.w = fmaf(w0, x0.w, a0.w);
            a1.x = fmaf(w1, x1.x, a1.x); a1.y = fmaf(w1, x1.y, a1.y);
            a1.z = fmaf(w1, x1.z, a1.z); a1.w = fmaf(w1, x1.w, a1.w);
        }
        if (i < re) {
            float w0 = sw[i];
            float4 x0 = X4[(size_t)(base + i) * 64 + dq];
            a0.x = fmaf(w0, x0.x, a0.x); a0.y = fmaf(w0, x0.y, a0.y);
            a0.z = fmaf(w0, x0.z, a0.z); a0.w = fmaf(w0, x0.w, a0.w);
        }
        a0.x += a1.x; a0.y += a1.y; a0.z += a1.z; a0.w += a1.w;
        red[quad][dq] = a0;
        __syncthreads();
        if (quad == 0 && rs < re) {
            float4 t0 = red[0][dq], t1 = red[1][dq], t2 = red[2][dq], t3 = red[3][dq];
            float* o = &out[(size_t)(g0 + run) * DIM + dq * 4];
            atomicAdd(o + 0, (t0.x + t1.x) + (t2.x + t3.x));
            atomicAdd(o + 1, (t0.y + t1.y) + (t2.y + t3.y));
            atomicAdd(o + 2, (t0.z + t1.z) + (t2.z + t3.z));
            atomicAdd(o + 3, (t0.w + t1.w) + (t2.w + t3.w));
        }
        __syncthreads();
    }
}

extern "C" void kernel_launch(void* const* d_in, const int* in_sizes, int n_in,
                              void* d_out, int out_size)
{
    const float* emb_nodes  = (const float*)d_in[0];
    const float* emb_edges  = (const float*)d_in[1];
    const int*   node_index = (const int*)d_in[2];
    const int*   edge_index = (const int*)d_in[3];
    const float* Wn1 = (const float*)d_in[4];
    const float* bn1 = (const float*)d_in[5];
    const float* Wn2 = (const float*)d_in[6];
    const float* bn2 = (const float*)d_in[7];
    const float* Wn3 = (const float*)d_in[8];
    const float* bn3 = (const float*)d_in[9];
    const float* We1 = (const float*)d_in[10];
    const float* be1 = (const float*)d_in[11];
    const float* We2 = (const float*)d_in[12];
    const float* be2 = (const float*)d_in[13];
    const float* We3 = (const float*)d_in[14];
    const float* be3 = (const float*)d_in[15];

    const int n_nodes = in_sizes[0] / DIM;
    const int n_edges = in_sizes[1] / DIM;
    const int G = out_size / (2 * DIM);

    cudaFuncSetAttribute(mlp_logits_kernel,
                         cudaFuncAttributeMaxDynamicSharedMemorySize, SMEM_BYTES);

    float* logits = nullptr;
    __half* w1h = nullptr;    __half* w2h = nullptr;
    cudaGetSymbolAddress((void**)&logits, g_logits);
    cudaGetSymbolAddress((void**)&w1h, g_w1h);
    cudaGetSymbolAddress((void**)&w2h, g_w2h);

    __half* w1h_n = w1h;               __half* w2h_n = w2h;
    __half* w1h_e = w1h + 256 * 128;   __half* w2h_e = w2h + 128 * 64;

    float* logits_n = logits;
    float* logits_e = logits + n_nodes;

    float* out_n = (float*)d_out;
    float* out_e = (float*)d_out + (size_t)G * DIM;

    cudaMemsetAsync(d_out, 0, (size_t)out_size * sizeof(float));

    convert_w_kernel<<<128, 256>>>(Wn1, Wn2, w1h_n, w2h_n);
    convert_w_kernel<<<128, 256>>>(We1, We2, w1h_e, w2h_e);

    int blocks_n = (n_nodes + TILE_ROWS - 1) / TILE_ROWS;
    int blocks_e = (n_edges + TILE_ROWS - 1) / TILE_ROWS;

    mlp_logits_kernel<<<blocks_n, THREADS, SMEM_BYTES>>>(
        emb_nodes, w1h_n, w2h_n, bn1, bn2, Wn3, bn3, logits_n, n_nodes);
    mlp_logits_kernel<<<blocks_e, THREADS, SMEM_BYTES>>>(
        emb_edges, w1h_e, w2h_e, be1, be2, We3, be3, logits_e, n_edges);

    int sblocks = (G + GPB - 1) / GPB;
    softmax_kernel<<<sblocks, 512>>>(logits_n, node_index, n_nodes);
    softmax_kernel<<<sblocks, 512>>>(logits_e, edge_index, n_edges);

    pool_kernel<<<(n_nodes + RPB - 1) / RPB, 256>>>(emb_nodes, logits_n, node_index, out_n, n_nodes);
    pool_kernel<<<(n_edges + RPB - 1) / RPB, 256>>>(emb_edges, logits_e, edge_index, out_e, n_edges);
}